// round 1
// baseline (speedup 1.0000x reference)
#include <cuda_runtime.h>

#define Bc  2
#define Cc  256
#define Hc  128
#define Wc  128
#define HWc 16384
#define Oc  256

// ---------------- scratch (no allocations allowed) ----------------
__device__ __align__(16) float g_xt[Bc * HWc * Cc];    // x in NHWC: [b][h*W+w][c]
__device__ __align__(16) float g_wr[9 * 256 * 28];     // w_off reordered: [tap][c][oc(pad 28)]
__device__ __align__(16) float g_wt[256 * 256];        // weight transposed: [c][o]
__device__ __align__(16) float g_tmp[Bc * 27 * HWc];   // conv output / softmaxed mask in-place
__device__ __align__(16) float g_agg[Bc * HWc * Cc];   // sum_k mask*bilinear : [b][p][c]
__device__ float2 g_stats[18];                          // per (b,k): (max, 1/sumexp)

// ---------------- kernel 1: NCHW -> NHWC transpose ----------------
__global__ void k_transpose(const float* __restrict__ x) {
    __shared__ float tile[32][33];
    int b = blockIdx.z;
    int hw0 = blockIdx.x * 32, c0 = blockIdx.y * 32;
    const float* src = x + (size_t)b * Cc * HWc;
    float* dst = g_xt + (size_t)b * HWc * Cc;
    int tx = threadIdx.x, ty = threadIdx.y;
#pragma unroll
    for (int i = 0; i < 32; i += 8)
        tile[ty + i][tx] = src[(size_t)(c0 + ty + i) * HWc + hw0 + tx];
    __syncthreads();
#pragma unroll
    for (int i = 0; i < 32; i += 8)
        dst[(size_t)(hw0 + ty + i) * Cc + c0 + tx] = tile[tx][ty + i];
}

// ---------------- kernel 2: weight reorders ----------------
__global__ void k_prep_w(const float* __restrict__ w_off, const float* __restrict__ weight) {
    int i = blockIdx.x * 256 + threadIdx.x;
    if (i < 9 * 256 * 28) {
        int oc = i % 28;
        int rest = i / 28;
        int c = rest % 256;
        int tap = rest / 256;
        g_wr[i] = (oc < 27) ? w_off[(oc * 256 + c) * 9 + tap] : 0.f;
    }
    if (i < 256 * 256) {
        int o = i & 255, c = i >> 8;
        g_wt[c * 256 + o] = weight[o * 256 + c];
    }
}

// ---------------- kernel 3: 3x3 conv, 27 outputs (offsets+mask logits) ----------------
__global__ void k_conv(const float* __restrict__ b_off) {
    int pos = blockIdx.x * 128 + threadIdx.x;   // 0 .. B*HW-1
    int b = pos >> 14;
    int p = pos & (HWc - 1);
    int h = p >> 7, w = p & 127;

    float acc[28];
#pragma unroll
    for (int oc = 0; oc < 27; oc++) acc[oc] = b_off[oc];
    acc[27] = 0.f;

    for (int kh = 0; kh < 3; kh++) {
        int yy = h + kh - 1;
        if (yy < 0 || yy >= Hc) continue;
        for (int kw = 0; kw < 3; kw++) {
            int xx = w + kw - 1;
            if (xx < 0 || xx >= Wc) continue;
            const float4* xp = (const float4*)(g_xt + ((size_t)(b << 14) + (yy << 7) + xx) * Cc);
            const float* wb = g_wr + (kh * 3 + kw) * 256 * 28;
            for (int c4 = 0; c4 < 64; c4++) {
                float4 xv = xp[c4];
#pragma unroll
                for (int j = 0; j < 4; j++) {
                    float xs = (j == 0) ? xv.x : (j == 1) ? xv.y : (j == 2) ? xv.z : xv.w;
                    const float4* wp = (const float4*)(wb + (c4 * 4 + j) * 28);
#pragma unroll
                    for (int q = 0; q < 7; q++) {
                        float4 wv = wp[q];
                        acc[4 * q + 0] += xs * wv.x;
                        acc[4 * q + 1] += xs * wv.y;
                        acc[4 * q + 2] += xs * wv.z;
                        acc[4 * q + 3] += xs * wv.w;
                    }
                }
            }
        }
    }
#pragma unroll
    for (int oc = 0; oc < 27; oc++)
        g_tmp[((size_t)(b * 27 + oc) << 14) + p] = acc[oc];
}

// ---------------- kernel 4: softmax stats per (b,k) over HW ----------------
__global__ void k_softmax_stats() {
    int bk = blockIdx.x;
    int b = bk / 9, k = bk % 9;
    const float* ptr = g_tmp + ((size_t)(b * 27 + 18 + k) << 14);
    __shared__ float red[256];
    int t = threadIdx.x;
    float m = -1e30f;
    for (int i = t; i < HWc; i += 256) m = fmaxf(m, ptr[i]);
    red[t] = m;
    __syncthreads();
    for (int s = 128; s > 0; s >>= 1) {
        if (t < s) red[t] = fmaxf(red[t], red[t + s]);
        __syncthreads();
    }
    m = red[0];
    __syncthreads();
    float sum = 0.f;
    for (int i = t; i < HWc; i += 256) sum += expf(ptr[i] - m);
    red[t] = sum;
    __syncthreads();
    for (int s = 128; s > 0; s >>= 1) {
        if (t < s) red[t] += red[t + s];
        __syncthreads();
    }
    if (t == 0) g_stats[bk] = make_float2(m, 1.f / red[0]);
}

// ---------------- kernel 5: softmax normalize (in place) ----------------
__global__ void k_softmax_norm() {
    int idx = blockIdx.x * 256 + threadIdx.x;   // 18*HW total
    int bk = idx >> 14;
    int off = idx & (HWc - 1);
    int b = bk / 9, k = bk % 9;
    float2 st = g_stats[bk];
    float* ptr = g_tmp + ((size_t)(b * 27 + 18 + k) << 14);
    ptr[off] = expf(ptr[off] - st.x) * st.y;
}

// ---------------- kernel 6: bilinear gather + mask-weighted sum over k ----------------
__global__ void k_gather() {
    int c = threadIdx.x;                 // 256 threads = channels
    int b = blockIdx.y;
    int p0 = blockIdx.x * 8;
    const float* tb = g_tmp + ((size_t)b * 27 << 14);
    const float* xb = g_xt + ((size_t)(b << 14)) * Cc;
    float* ab = g_agg + ((size_t)(b << 14)) * Cc;

    for (int pp = 0; pp < 8; pp++) {
        int p = p0 + pp;
        int h = p >> 7, w = p & 127;
        float acc = 0.f;
#pragma unroll
        for (int k = 0; k < 9; k++) {
            float dy = tb[(2 * k) * HWc + p];
            float dx = tb[(2 * k + 1) * HWc + p];
            float m  = tb[(18 + k) * HWc + p];
            float py = dy + (float)(h + k / 3 - 1);
            float px = dx + (float)(w + k % 3 - 1);
            float fy = floorf(py), fx = floorf(px);
            int y0 = (int)fy, x0 = (int)fx;
            float ly = py - fy, lx = px - fx;
            float w00 = (1.f - ly) * (1.f - lx) * m;
            float w01 = (1.f - ly) * lx * m;
            float w10 = ly * (1.f - lx) * m;
            float w11 = ly * lx * m;
            int y0c = min(max(y0, 0), Hc - 1), y1c = min(max(y0 + 1, 0), Hc - 1);
            int x0c = min(max(x0, 0), Wc - 1), x1c = min(max(x0 + 1, 0), Wc - 1);
            bool vy0 = (y0 >= 0) && (y0 < Hc);
            bool vy1 = (y0 + 1 >= 0) && (y0 + 1 < Hc);
            bool vx0 = (x0 >= 0) && (x0 < Wc);
            bool vx1 = (x0 + 1 >= 0) && (x0 + 1 < Wc);
            float v00 = xb[(size_t)((y0c << 7) + x0c) * Cc + c];
            float v01 = xb[(size_t)((y0c << 7) + x1c) * Cc + c];
            float v10 = xb[(size_t)((y1c << 7) + x0c) * Cc + c];
            float v11 = xb[(size_t)((y1c << 7) + x1c) * Cc + c];
            acc += ((vy0 && vx0) ? w00 : 0.f) * v00
                 + ((vy0 && vx1) ? w01 : 0.f) * v01
                 + ((vy1 && vx0) ? w10 : 0.f) * v10
                 + ((vy1 && vx1) ? w11 : 0.f) * v11;
        }
        ab[(size_t)p * Cc + c] = acc;
    }
}

// ---------------- kernel 7: 1x1 conv GEMM: out[b,o,p] = sum_c W[o,c]*agg[b,p,c] + bias[o] ----------------
__global__ void k_gemm(float* __restrict__ out, const float* __restrict__ bias) {
    __shared__ float Ws[32][64];     // [c_l][o_l]
    __shared__ float Bs[64][33];     // [p_l][c_l] (+pad)
    int b = blockIdx.z;
    int p_tile = blockIdx.x * 64, o_tile = blockIdx.y * 64;
    int tx = threadIdx.x, ty = threadIdx.y;
    int tid = ty * 16 + tx;
    const float* aggb = g_agg + ((size_t)(b << 14)) * Cc;

    float acc[4][4] = {};
    for (int kt = 0; kt < 256; kt += 32) {
#pragma unroll
        for (int r = 0; r < 8; r++) {
            int e = tid + r * 256;
            int c_l = e >> 6, o_l = e & 63;
            Ws[c_l][o_l] = g_wt[(kt + c_l) * 256 + o_tile + o_l];
        }
#pragma unroll
        for (int r = 0; r < 8; r++) {
            int e = tid + r * 256;
            int p_l = e >> 5, c_l = e & 31;
            Bs[p_l][c_l] = aggb[(size_t)(p_tile + p_l) * Cc + kt + c_l];
        }
        __syncthreads();
#pragma unroll
        for (int kk = 0; kk < 32; kk++) {
            float4 a4 = *(const float4*)&Ws[kk][ty * 4];
            float bsv[4];
#pragma unroll
            for (int j = 0; j < 4; j++) bsv[j] = Bs[tx * 4 + j][kk];
#pragma unroll
            for (int i = 0; i < 4; i++) {
                float av = (i == 0) ? a4.x : (i == 1) ? a4.y : (i == 2) ? a4.z : a4.w;
                acc[i][0] += av * bsv[0];
                acc[i][1] += av * bsv[1];
                acc[i][2] += av * bsv[2];
                acc[i][3] += av * bsv[3];
            }
        }
        __syncthreads();
    }
#pragma unroll
    for (int i = 0; i < 4; i++) {
        int o = o_tile + ty * 4 + i;
        float bv = bias[o];
#pragma unroll
        for (int j = 0; j < 4; j++) {
            int p = p_tile + tx * 4 + j;
            out[((size_t)(b * Oc + o) << 14) + p] = acc[i][j] + bv;
        }
    }
}

// ---------------- launch ----------------
extern "C" void kernel_launch(void* const* d_in, const int* in_sizes, int n_in,
                              void* d_out, int out_size) {
    const float* x      = (const float*)d_in[0];
    const float* w_off  = (const float*)d_in[1];
    const float* b_off  = (const float*)d_in[2];
    const float* weight = (const float*)d_in[3];
    const float* bias   = (const float*)d_in[4];
    float* out = (float*)d_out;

    k_transpose<<<dim3(512, 8, 2), dim3(32, 8)>>>(x);
    k_prep_w<<<256, 256>>>(w_off, weight);
    k_conv<<<256, 128>>>(b_off);
    k_softmax_stats<<<18, 256>>>();
    k_softmax_norm<<<1152, 256>>>();
    k_gather<<<dim3(2048, 2), 256>>>();
    k_gemm<<<dim3(256, 4, 2), dim3(16, 16)>>>(out, bias);
}

// round 2
// speedup vs baseline: 2.3684x; 2.3684x over previous
#include <cuda_runtime.h>

#define Bc  2
#define Cc  256
#define Hc  128
#define Wc  128
#define HWc 16384
#define Oc  256

// ---------------- scratch ----------------
__device__ __align__(16) float g_xt[Bc * HWc * Cc];    // x in NHWC: [b][p][c]
__device__ __align__(16) float g_wr[9 * 256 * 28];     // w_off reordered: [tap][c][oc(pad28)]
__device__ __align__(16) float g_wt[256 * 256];        // weight transposed: [c][o]
__device__ __align__(16) float g_tmp[Bc * 27 * HWc];   // conv output (offsets + mask logits)
__device__ __align__(16) float g_agg[Bc * HWc * Cc];   // sum_k mask*bilinear : [b][p][c]
__device__ float2 g_stats[18];                          // per (b,k): (max, 1/sumexp)

// ---------------- kernel 1: NCHW -> NHWC transpose ----------------
__global__ void k_transpose(const float* __restrict__ x) {
    __shared__ float tile[32][33];
    int b = blockIdx.z;
    int hw0 = blockIdx.x * 32, c0 = blockIdx.y * 32;
    const float* src = x + (size_t)b * Cc * HWc;
    float* dst = g_xt + (size_t)b * HWc * Cc;
    int tx = threadIdx.x, ty = threadIdx.y;
#pragma unroll
    for (int i = 0; i < 32; i += 8)
        tile[ty + i][tx] = src[(size_t)(c0 + ty + i) * HWc + hw0 + tx];
    __syncthreads();
#pragma unroll
    for (int i = 0; i < 32; i += 8)
        dst[(size_t)(hw0 + ty + i) * Cc + c0 + tx] = tile[tx][ty + i];
}

// ---------------- kernel 2: weight reorders ----------------
__global__ void k_prep_w(const float* __restrict__ w_off, const float* __restrict__ weight) {
    int i = blockIdx.x * 256 + threadIdx.x;
    if (i < 9 * 256 * 28) {
        int oc = i % 28;
        int rest = i / 28;
        int c = rest % 256;
        int tap = rest / 256;
        g_wr[i] = (oc < 27) ? w_off[(oc * 256 + c) * 9 + tap] : 0.f;
    }
    if (i < 256 * 256) {
        int o = i & 255, c = i >> 8;
        g_wt[c * 256 + o] = weight[o * 256 + c];
    }
}

// ---------------- kernel 3: 3x3 conv, 27 outputs, smem-staged ----------------
// grid: (2 halves, 128 rows, B). block: 128 threads = 64 positions x 2 output-halves.
__global__ void k_conv(const float* __restrict__ b_off) {
    __shared__ float xs[32][68];          // [c][colIdx], colIdx 0..65 -> gcol = w0-1+colIdx
    __shared__ float ws[9][32][32];       // [tap][c][q*16+j] ; oc = q*14+j (j<14, oc<27), else 0

    int half = blockIdx.x;
    int h = blockIdx.y;
    int b = blockIdx.z;
    int tid = threadIdx.x;
    int w_l = tid & 63;
    int q = tid >> 6;                     // 0 or 1: outputs q*14 .. q*14+13
    int w0 = half * 64;
    int w = w0 + w_l;
    int p = (h << 7) + w;

    float acc[16];
#pragma unroll
    for (int j = 0; j < 16; j++) {
        int oc = q * 14 + j;
        acc[j] = (j < 14 && oc < 27) ? b_off[oc] : 0.f;
    }

    for (int cb = 0; cb < 256; cb += 32) {
        __syncthreads();   // protect ws from previous chunk's readers
        // load weights for this channel chunk, all 9 taps: 9*32*32 = 9216 floats
        for (int e = tid; e < 9 * 32 * 32; e += 128) {
            int t = e >> 10;
            int rem = e & 1023;
            int c = rem >> 5;
            int jj = rem & 31;
            int q2 = jj >> 4, j = jj & 15;
            int oc = q2 * 14 + j;
            float v = 0.f;
            if (j < 14 && oc < 27)
                v = g_wr[(t * 256 + cb + c) * 28 + oc];
            ws[t][c][jj] = v;
        }

        for (int kh = 0; kh < 3; kh++) {
            int yy = h + kh - 1;
            __syncthreads();  // protect xs from previous tap's readers (also fences ws load)
            // load x tile: 66 cols x 32 ch
            for (int e = tid; e < 66 * 32; e += 128) {
                int col = e >> 5;
                int c = e & 31;
                int gcol = w0 - 1 + col;
                float v = 0.f;
                if (yy >= 0 && yy < Hc && gcol >= 0 && gcol < Wc)
                    v = g_xt[((size_t)(b << 14) + (yy << 7) + gcol) * Cc + cb + c];
                xs[c][col] = v;
            }
            __syncthreads();

#pragma unroll
            for (int kw = 0; kw < 3; kw++) {
                int t = kh * 3 + kw;
#pragma unroll 8
                for (int c = 0; c < 32; c++) {
                    float xv = xs[c][w_l + kw];
                    const float4* wp = (const float4*)&ws[t][c][q * 16];
#pragma unroll
                    for (int v4 = 0; v4 < 4; v4++) {
                        float4 wv = wp[v4];
                        acc[v4 * 4 + 0] += xv * wv.x;
                        acc[v4 * 4 + 1] += xv * wv.y;
                        acc[v4 * 4 + 2] += xv * wv.z;
                        acc[v4 * 4 + 3] += xv * wv.w;
                    }
                }
            }
        }
    }
#pragma unroll
    for (int j = 0; j < 14; j++) {
        int oc = q * 14 + j;
        if (oc < 27)
            g_tmp[((size_t)(b * 27 + oc) << 14) + p] = acc[j];
    }
}

// ---------------- kernel 4: softmax stats per (b,k) over HW ----------------
__global__ void k_softmax_stats() {
    int bk = blockIdx.x;
    int b = bk / 9, k = bk % 9;
    const float* ptr = g_tmp + ((size_t)(b * 27 + 18 + k) << 14);
    __shared__ float red[256];
    int t = threadIdx.x;
    float m = -1e30f;
    for (int i = t; i < HWc; i += 256) m = fmaxf(m, ptr[i]);
    red[t] = m;
    __syncthreads();
    for (int s = 128; s > 0; s >>= 1) {
        if (t < s) red[t] = fmaxf(red[t], red[t + s]);
        __syncthreads();
    }
    m = red[0];
    __syncthreads();
    float sum = 0.f;
    for (int i = t; i < HWc; i += 256) sum += expf(ptr[i] - m);
    red[t] = sum;
    __syncthreads();
    for (int s = 128; s > 0; s >>= 1) {
        if (t < s) red[t] += red[t + s];
        __syncthreads();
    }
    if (t == 0) g_stats[bk] = make_float2(m, 1.f / red[0]);
}

// ---------------- kernel 5: bilinear gather + mask-weighted sum over k ----------------
// grid (1024, B), 256 threads. 16 positions per block.
// phase 1: 144 threads compute masked weights + clamped flat indices into smem.
// phase 2: 64 c4-lanes x 4 pos-groups do float4 gathers.
__global__ void k_gather() {
    __shared__ float4 sw[16 * 9];
    __shared__ int4  sidx[16 * 9];
    int b = blockIdx.y;
    int p0 = blockIdx.x * 16;
    int tid = threadIdx.x;
    const float* tb = g_tmp + ((size_t)b * 27 << 14);

    if (tid < 144) {
        int pl = tid / 9, k = tid % 9;
        int p = p0 + pl;
        int h = p >> 7, w = p & 127;
        float dy = tb[(2 * k) * HWc + p];
        float dx = tb[(2 * k + 1) * HWc + p];
        float2 st = g_stats[b * 9 + k];
        float m = expf(tb[(18 + k) * HWc + p] - st.x) * st.y;
        float py = dy + (float)(h + k / 3 - 1);
        float px = dx + (float)(w + k % 3 - 1);
        float fy = floorf(py), fx = floorf(px);
        int y0 = (int)fy, x0 = (int)fx;
        float ly = py - fy, lx = px - fx;
        bool vy0 = (y0 >= 0) && (y0 < Hc);
        bool vy1 = (y0 + 1 >= 0) && (y0 + 1 < Hc);
        bool vx0 = (x0 >= 0) && (x0 < Wc);
        bool vx1 = (x0 + 1 >= 0) && (x0 + 1 < Wc);
        float4 wt;
        wt.x = (vy0 && vx0) ? (1.f - ly) * (1.f - lx) * m : 0.f;
        wt.y = (vy0 && vx1) ? (1.f - ly) * lx * m : 0.f;
        wt.z = (vy1 && vx0) ? ly * (1.f - lx) * m : 0.f;
        wt.w = (vy1 && vx1) ? ly * lx * m : 0.f;
        int y0c = min(max(y0, 0), Hc - 1), y1c = min(max(y0 + 1, 0), Hc - 1);
        int x0c = min(max(x0, 0), Wc - 1), x1c = min(max(x0 + 1, 0), Wc - 1);
        int4 id;
        id.x = (y0c << 7) + x0c;
        id.y = (y0c << 7) + x1c;
        id.z = (y1c << 7) + x0c;
        id.w = (y1c << 7) + x1c;
        sw[tid] = wt;
        sidx[tid] = id;
    }
    __syncthreads();

    int c4 = tid & 63;            // float4-channel index 0..63
    int pg = tid >> 6;            // 0..3
    const float4* xb4 = (const float4*)(g_xt + (size_t)(b << 14) * Cc);
    float4* ab4 = (float4*)(g_agg + (size_t)(b << 14) * Cc);

#pragma unroll
    for (int pp = 0; pp < 4; pp++) {
        int pl = pg * 4 + pp;
        int p = p0 + pl;
        float4 acc = make_float4(0.f, 0.f, 0.f, 0.f);
#pragma unroll
        for (int k = 0; k < 9; k++) {
            float4 wt = sw[pl * 9 + k];
            int4 id = sidx[pl * 9 + k];
            float4 v00 = xb4[(size_t)id.x * 64 + c4];
            float4 v01 = xb4[(size_t)id.y * 64 + c4];
            float4 v10 = xb4[(size_t)id.z * 64 + c4];
            float4 v11 = xb4[(size_t)id.w * 64 + c4];
            acc.x += wt.x * v00.x + wt.y * v01.x + wt.z * v10.x + wt.w * v11.x;
            acc.y += wt.x * v00.y + wt.y * v01.y + wt.z * v10.y + wt.w * v11.y;
            acc.z += wt.x * v00.z + wt.y * v01.z + wt.z * v10.z + wt.w * v11.z;
            acc.w += wt.x * v00.w + wt.y * v01.w + wt.z * v10.w + wt.w * v11.w;
        }
        ab4[(size_t)p * 64 + c4] = acc;
    }
}

// ---------------- kernel 6: 1x1 conv GEMM ----------------
__global__ void k_gemm(float* __restrict__ out, const float* __restrict__ bias) {
    __shared__ float Ws[32][64];     // [c_l][o_l]
    __shared__ float Bs[64][33];     // [p_l][c_l] (+pad)
    int b = blockIdx.z;
    int p_tile = blockIdx.x * 64, o_tile = blockIdx.y * 64;
    int tx = threadIdx.x, ty = threadIdx.y;
    int tid = ty * 16 + tx;
    const float* aggb = g_agg + ((size_t)(b << 14)) * Cc;

    float acc[4][4] = {};
    for (int kt = 0; kt < 256; kt += 32) {
#pragma unroll
        for (int r = 0; r < 8; r++) {
            int e = tid + r * 256;
            int c_l = e >> 6, o_l = e & 63;
            Ws[c_l][o_l] = g_wt[(kt + c_l) * 256 + o_tile + o_l];
        }
#pragma unroll
        for (int r = 0; r < 8; r++) {
            int e = tid + r * 256;
            int p_l = e >> 5, c_l = e & 31;
            Bs[p_l][c_l] = aggb[(size_t)(p_tile + p_l) * Cc + kt + c_l];
        }
        __syncthreads();
#pragma unroll
        for (int kk = 0; kk < 32; kk++) {
            float4 a4 = *(const float4*)&Ws[kk][ty * 4];
            float bsv[4];
#pragma unroll
            for (int j = 0; j < 4; j++) bsv[j] = Bs[tx * 4 + j][kk];
#pragma unroll
            for (int i = 0; i < 4; i++) {
                float av = (i == 0) ? a4.x : (i == 1) ? a4.y : (i == 2) ? a4.z : a4.w;
                acc[i][0] += av * bsv[0];
                acc[i][1] += av * bsv[1];
                acc[i][2] += av * bsv[2];
                acc[i][3] += av * bsv[3];
            }
        }
        __syncthreads();
    }
#pragma unroll
    for (int i = 0; i < 4; i++) {
        int o = o_tile + ty * 4 + i;
        float bv = bias[o];
#pragma unroll
        for (int j = 0; j < 4; j++) {
            int p = p_tile + tx * 4 + j;
            out[((size_t)(b * Oc + o) << 14) + p] = acc[i][j] + bv;
        }
    }
}

// ---------------- launch ----------------
extern "C" void kernel_launch(void* const* d_in, const int* in_sizes, int n_in,
                              void* d_out, int out_size) {
    const float* x      = (const float*)d_in[0];
    const float* w_off  = (const float*)d_in[1];
    const float* b_off  = (const float*)d_in[2];
    const float* weight = (const float*)d_in[3];
    const float* bias   = (const float*)d_in[4];
    float* out = (float*)d_out;

    k_transpose<<<dim3(512, 8, 2), dim3(32, 8)>>>(x);
    k_prep_w<<<256, 256>>>(w_off, weight);
    k_conv<<<dim3(2, 128, 2), 128>>>(b_off);
    k_softmax_stats<<<18, 256>>>();
    k_gather<<<dim3(1024, 2), 256>>>();
    k_gemm<<<dim3(256, 4, 2), dim3(16, 16)>>>(out, bias);
}

// round 6
// speedup vs baseline: 4.1800x; 1.7649x over previous
#include <cuda_runtime.h>
#include <cuda_bf16.h>
#include <mma.h>
#include <cstdint>

using namespace nvcuda;

#define Bc  2
#define Cc  256
#define Hc  128
#define Wc  128
#define HWc 16384
#define Oc  256

// ---------------- scratch ----------------
__device__ __align__(16) float g_xt[Bc * HWc * Cc];            // x NHWC fp32 (for bilinear)
__device__ __align__(16) __nv_bfloat16 g_xhi[Bc * HWc * Cc];   // x NHWC bf16 hi
__device__ __align__(16) __nv_bfloat16 g_xlo[Bc * HWc * Cc];   // x NHWC bf16 lo
__device__ __align__(16) float g_tmp[Bc * 27 * HWc];           // conv out (offsets + logits)
__device__ __align__(16) __nv_bfloat16 g_ahi[Bc * HWc * Cc];   // agg bf16 hi [row][c]
__device__ __align__(16) __nv_bfloat16 g_alo[Bc * HWc * Cc];   // agg bf16 lo
__device__ __align__(16) __nv_bfloat16 g_whi[Oc * Cc];         // 1x1 weight hi [o][c]
__device__ __align__(16) __nv_bfloat16 g_wlo[Oc * Cc];         // 1x1 weight lo
__device__ __align__(16) __nv_bfloat16 g_cAh[9 * 32 * 256];    // conv A hi [tap][oc(32)][c]
__device__ __align__(16) __nv_bfloat16 g_cAl[9 * 32 * 256];    // conv A lo
__device__ float2 g_stats[18];                                  // per (b,k): (max, 1/sumexp)

__device__ __forceinline__ void split2(float v, unsigned short& hi, unsigned short& lo) {
    __nv_bfloat16 h = __float2bfloat16(v);
    hi = __bfloat16_as_ushort(h);
    lo = __bfloat16_as_ushort(__float2bfloat16(v - __bfloat162float(h)));
}

// ---------------- kernel 1: NCHW -> NHWC transpose (+ bf16 hi/lo split) ----------------
__global__ void k_transpose(const float* __restrict__ x) {
    __shared__ float tile[32][33];
    int b = blockIdx.z;
    int hw0 = blockIdx.x * 32, c0 = blockIdx.y * 32;
    const float* src = x + (size_t)b * Cc * HWc;
    int tx = threadIdx.x, ty = threadIdx.y;
#pragma unroll
    for (int i = 0; i < 32; i += 8)
        tile[ty + i][tx] = src[(size_t)(c0 + ty + i) * HWc + hw0 + tx];
    __syncthreads();
    size_t base = (size_t)b * HWc * Cc;
#pragma unroll
    for (int i = 0; i < 32; i += 8) {
        float v = tile[tx][ty + i];
        size_t di = base + (size_t)(hw0 + ty + i) * Cc + c0 + tx;
        g_xt[di] = v;
        unsigned short hi, lo;
        split2(v, hi, lo);
        g_xhi[di] = __ushort_as_bfloat16(hi);
        g_xlo[di] = __ushort_as_bfloat16(lo);
    }
}

// ---------------- kernel 2: weight prep (splits) ----------------
__global__ void k_prep_w(const float* __restrict__ w_off, const float* __restrict__ weight) {
    int i = blockIdx.x * 256 + threadIdx.x;
    if (i < Oc * Cc) {
        unsigned short hi, lo;
        split2(weight[i], hi, lo);
        g_whi[i] = __ushort_as_bfloat16(hi);
        g_wlo[i] = __ushort_as_bfloat16(lo);
    }
    if (i < 9 * 32 * 256) {
        int t = i >> 13;            // 8192 per tap
        int oc = (i >> 8) & 31;
        int c = i & 255;
        float v = (oc < 27) ? w_off[((oc << 8) + c) * 9 + t] : 0.f;
        unsigned short hi, lo;
        split2(v, hi, lo);
        g_cAh[i] = __ushort_as_bfloat16(hi);
        g_cAl[i] = __ushort_as_bfloat16(lo);
    }
}

// ---------------- kernel 3: 3x3 conv (27 outputs) via WMMA implicit GEMM ----------------
// grid = B*H (one output row per CTA, N=128). K = 9 taps x 256 ch, split-bf16 3-term.
// smem: sA [9][32][40] hi/lo, sB [3][132][40] hi/lo (halo slab reused across taps).
#define CV_ALD 40
#define CV_BLD 40
#define CV_ELD 132
#define CV_SA_H 0
#define CV_SA_L (9 * 32 * CV_ALD * 2)
#define CV_SB_H (CV_SA_L * 2)
#define CV_SB_L (CV_SB_H + 3 * 132 * CV_BLD * 2)
#define CV_SMEM (CV_SB_L + 3 * 132 * CV_BLD * 2)

__global__ void __launch_bounds__(256) k_conv_mma(const float* __restrict__ b_off) {
    extern __shared__ char sm[];
    __nv_bfloat16* sAh = (__nv_bfloat16*)(sm + CV_SA_H);
    __nv_bfloat16* sAl = (__nv_bfloat16*)(sm + CV_SA_L);
    __nv_bfloat16* sBh = (__nv_bfloat16*)(sm + CV_SB_H);
    __nv_bfloat16* sBl = (__nv_bfloat16*)(sm + CV_SB_L);
    float* sE = (float*)sm;

    int tid = threadIdx.x, wid = tid >> 5;
    int h = blockIdx.x & 127;
    int b = blockIdx.x >> 7;

    wmma::fragment<wmma::accumulator, 16, 16, 16, float> acc[2];
    wmma::fill_fragment(acc[0], 0.f);
    wmma::fill_fragment(acc[1], 0.f);

    for (int cc = 0; cc < 8; cc++) {
        int kc = cc * 32;
        __syncthreads();
        // stage A: all 9 taps, 32 oc x 32 c  (u32 = 2 halves: 4608 units)
        for (int e = tid; e < 4608; e += 256) {
            int t = e >> 9;
            int rem = e & 511;
            int oc = rem >> 4, cu = rem & 15;
            uint32_t vh = ((const uint32_t*)g_cAh)[(t * 32 + oc) * 128 + (kc >> 1) + cu];
            uint32_t vl = ((const uint32_t*)g_cAl)[(t * 32 + oc) * 128 + (kc >> 1) + cu];
            *(uint32_t*)&sAh[(t * 32 + oc) * CV_ALD + cu * 2] = vh;
            *(uint32_t*)&sAl[(t * 32 + oc) * CV_ALD + cu * 2] = vl;
        }
        // stage B halo slab: 3 rows (h-1..h+1) x 130 cols (-1..128) x 32 ch (6240 u32)
        for (int e = tid; e < 6240; e += 256) {
            int row = e >> 4, cu = e & 15;
            int yyi = row / 130;
            int ww = row % 130 - 1;
            int yy = h + yyi - 1;
            uint32_t vh = 0, vl = 0;
            if (yy >= 0 && yy < Hc && ww >= 0 && ww < Wc) {
                size_t gi = (((size_t)(b << 14) + (yy << 7) + ww) * Cc + kc) >> 1;
                vh = ((const uint32_t*)g_xhi)[gi + cu];
                vl = ((const uint32_t*)g_xlo)[gi + cu];
            }
            int si = (yyi * 132 + (ww + 1)) * CV_BLD + cu * 2;
            *(uint32_t*)&sBh[si] = vh;
            *(uint32_t*)&sBl[si] = vl;
        }
        __syncthreads();

#pragma unroll
        for (int t = 0; t < 9; t++) {
            int dy = t / 3, dx = t % 3;
#pragma unroll
            for (int kl = 0; kl < 2; kl++) {
                int kb = kl * 16;
                wmma::fragment<wmma::matrix_a, 16, 16, 16, __nv_bfloat16, wmma::row_major> ah[2], al[2];
                wmma::load_matrix_sync(ah[0], &sAh[(t * 32 + 0) * CV_ALD + kb], CV_ALD);
                wmma::load_matrix_sync(ah[1], &sAh[(t * 32 + 16) * CV_ALD + kb], CV_ALD);
                wmma::load_matrix_sync(al[0], &sAl[(t * 32 + 0) * CV_ALD + kb], CV_ALD);
                wmma::load_matrix_sync(al[1], &sAl[(t * 32 + 16) * CV_ALD + kb], CV_ALD);
                wmma::fragment<wmma::matrix_b, 16, 16, 16, __nv_bfloat16, wmma::col_major> bh, bl;
                int bbase = (dy * 132 + wid * 16 + dx) * CV_BLD + kb;
                wmma::load_matrix_sync(bh, &sBh[bbase], CV_BLD);
                wmma::load_matrix_sync(bl, &sBl[bbase], CV_BLD);
#pragma unroll
                for (int m = 0; m < 2; m++) {
                    wmma::mma_sync(acc[m], ah[m], bh, acc[m]);
                    wmma::mma_sync(acc[m], ah[m], bl, acc[m]);
                    wmma::mma_sync(acc[m], al[m], bh, acc[m]);
                }
            }
        }
    }
    __syncthreads();
    wmma::store_matrix_sync(&sE[0 * CV_ELD + wid * 16], acc[0], CV_ELD, wmma::mem_row_major);
    wmma::store_matrix_sync(&sE[16 * CV_ELD + wid * 16], acc[1], CV_ELD, wmma::mem_row_major);
    __syncthreads();
    for (int e = tid; e < 27 * 128; e += 256) {
        int oc = e >> 7, col = e & 127;
        g_tmp[((size_t)(b * 27 + oc) << 14) + (h << 7) + col] = sE[oc * CV_ELD + col] + b_off[oc];
    }
}

// ---------------- kernel 4: softmax stats per (b,k) over HW ----------------
__global__ void k_softmax_stats() {
    int bk = blockIdx.x;
    int b = bk / 9, k = bk % 9;
    const float* ptr = g_tmp + ((size_t)(b * 27 + 18 + k) << 14);
    __shared__ float red[256];
    int t = threadIdx.x;
    float m = -1e30f;
    for (int i = t; i < HWc; i += 256) m = fmaxf(m, ptr[i]);
    red[t] = m;
    __syncthreads();
    for (int s = 128; s > 0; s >>= 1) {
        if (t < s) red[t] = fmaxf(red[t], red[t + s]);
        __syncthreads();
    }
    m = red[0];
    __syncthreads();
    float sum = 0.f;
    for (int i = t; i < HWc; i += 256) sum += expf(ptr[i] - m);
    red[t] = sum;
    __syncthreads();
    for (int s = 128; s > 0; s >>= 1) {
        if (t < s) red[t] += red[t + s];
        __syncthreads();
    }
    if (t == 0) g_stats[bk] = make_float2(m, 1.f / red[0]);
}

// ---------------- kernel 5: bilinear gather + mask sum; writes split-bf16 agg ----------------
__global__ void k_gather() {
    __shared__ float4 sw[16 * 9];
    __shared__ int4  sidx[16 * 9];
    int b = blockIdx.y;
    int p0 = blockIdx.x * 16;
    int tid = threadIdx.x;
    const float* tb = g_tmp + ((size_t)b * 27 << 14);

    if (tid < 144) {
        int pl = tid / 9, k = tid % 9;
        int p = p0 + pl;
        int h = p >> 7, w = p & 127;
        float dy = tb[(2 * k) * HWc + p];
        float dx = tb[(2 * k + 1) * HWc + p];
        float2 st = g_stats[b * 9 + k];
        float m = expf(tb[(18 + k) * HWc + p] - st.x) * st.y;
        float py = dy + (float)(h + k / 3 - 1);
        float px = dx + (float)(w + k % 3 - 1);
        float fy = floorf(py), fx = floorf(px);
        int y0 = (int)fy, x0 = (int)fx;
        float ly = py - fy, lx = px - fx;
        bool vy0 = (y0 >= 0) && (y0 < Hc);
        bool vy1 = (y0 + 1 >= 0) && (y0 + 1 < Hc);
        bool vx0 = (x0 >= 0) && (x0 < Wc);
        bool vx1 = (x0 + 1 >= 0) && (x0 + 1 < Wc);
        float4 wt;
        wt.x = (vy0 && vx0) ? (1.f - ly) * (1.f - lx) * m : 0.f;
        wt.y = (vy0 && vx1) ? (1.f - ly) * lx * m : 0.f;
        wt.z = (vy1 && vx0) ? ly * (1.f - lx) * m : 0.f;
        wt.w = (vy1 && vx1) ? ly * lx * m : 0.f;
        int y0c = min(max(y0, 0), Hc - 1), y1c = min(max(y0 + 1, 0), Hc - 1);
        int x0c = min(max(x0, 0), Wc - 1), x1c = min(max(x0 + 1, 0), Wc - 1);
        int4 id;
        id.x = (y0c << 7) + x0c;
        id.y = (y0c << 7) + x1c;
        id.z = (y1c << 7) + x0c;
        id.w = (y1c << 7) + x1c;
        sw[tid] = wt;
        sidx[tid] = id;
    }
    __syncthreads();

    int c4 = tid & 63;
    int pg = tid >> 6;
    const float4* xb4 = (const float4*)(g_xt + (size_t)(b << 14) * Cc);

#pragma unroll
    for (int pp = 0; pp < 4; pp++) {
        int pl = pg * 4 + pp;
        int p = p0 + pl;
        float4 acc = make_float4(0.f, 0.f, 0.f, 0.f);
#pragma unroll
        for (int k = 0; k < 9; k++) {
            float4 wt = sw[pl * 9 + k];
            int4 id = sidx[pl * 9 + k];
            float4 v00 = xb4[(size_t)id.x * 64 + c4];
            float4 v01 = xb4[(size_t)id.y * 64 + c4];
            float4 v10 = xb4[(size_t)id.z * 64 + c4];
            float4 v11 = xb4[(size_t)id.w * 64 + c4];
            acc.x += wt.x * v00.x + wt.y * v01.x + wt.z * v10.x + wt.w * v11.x;
            acc.y += wt.x * v00.y + wt.y * v01.y + wt.z * v10.y + wt.w * v11.y;
            acc.z += wt.x * v00.z + wt.y * v01.z + wt.z * v10.z + wt.w * v11.z;
            acc.w += wt.x * v00.w + wt.y * v01.w + wt.z * v10.w + wt.w * v11.w;
        }
        unsigned short h0, l0, h1, l1, h2, l2, h3, l3;
        split2(acc.x, h0, l0);
        split2(acc.y, h1, l1);
        split2(acc.z, h2, l2);
        split2(acc.w, h3, l3);
        uint2 hh, ll;
        hh.x = (uint32_t)h0 | ((uint32_t)h1 << 16);
        hh.y = (uint32_t)h2 | ((uint32_t)h3 << 16);
        ll.x = (uint32_t)l0 | ((uint32_t)l1 << 16);
        ll.y = (uint32_t)l2 | ((uint32_t)l3 << 16);
        size_t ui = (size_t)((b << 14) + p) * 64 + c4;
        ((uint2*)g_ahi)[ui] = hh;
        ((uint2*)g_alo)[ui] = ll;
    }
}

// ---------------- kernel 6: 1x1 conv GEMM via WMMA (split-bf16) ----------------
// CTA tile 128(o) x 128(p), K=256 in 4 chunks of 64. 8 warps = 4x2, warp 32x64.
#define GM_LD 72
#define GM_ELD 132
#define GM_SA_H 0
#define GM_SA_L (128 * GM_LD * 2)
#define GM_SB_H (GM_SA_L * 2)
#define GM_SB_L (GM_SB_H + 128 * GM_LD * 2)
#define GM_SMEM (GM_SB_L + 128 * GM_LD * 2)

__global__ void __launch_bounds__(256) k_gemm_mma(float* __restrict__ out, const float* __restrict__ bias) {
    extern __shared__ char sm[];
    __nv_bfloat16* sAh = (__nv_bfloat16*)(sm + GM_SA_H);
    __nv_bfloat16* sAl = (__nv_bfloat16*)(sm + GM_SA_L);
    __nv_bfloat16* sBh = (__nv_bfloat16*)(sm + GM_SB_H);
    __nv_bfloat16* sBl = (__nv_bfloat16*)(sm + GM_SB_L);
    float* sE = (float*)sm;

    int tid = threadIdx.x, wid = tid >> 5;
    int r0 = blockIdx.x * 128;          // global row (b,p combined)
    int ot = blockIdx.y;
    int wm = wid >> 1, wn = wid & 1;

    wmma::fragment<wmma::accumulator, 16, 16, 16, float> acc[2][4];
#pragma unroll
    for (int m = 0; m < 2; m++)
#pragma unroll
        for (int n = 0; n < 4; n++) wmma::fill_fragment(acc[m][n], 0.f);

    for (int cc = 0; cc < 4; cc++) {
        int kcu = cc * 16;              // in uint2 units (64 halves = 16 u2)
        __syncthreads();
        for (int e = tid; e < 2048; e += 256) {
            int r = e >> 4, cu = e & 15;
            uint2 vh = ((const uint2*)g_whi)[(size_t)(ot * 128 + r) * 64 + kcu + cu];
            uint2 vl = ((const uint2*)g_wlo)[(size_t)(ot * 128 + r) * 64 + kcu + cu];
            *(uint2*)&sAh[r * GM_LD + cu * 4] = vh;
            *(uint2*)&sAl[r * GM_LD + cu * 4] = vl;
            uint2 bh = ((const uint2*)g_ahi)[(size_t)(r0 + r) * 64 + kcu + cu];
            uint2 bl = ((const uint2*)g_alo)[(size_t)(r0 + r) * 64 + kcu + cu];
            *(uint2*)&sBh[r * GM_LD + cu * 4] = bh;
            *(uint2*)&sBl[r * GM_LD + cu * 4] = bl;
        }
        __syncthreads();

#pragma unroll
        for (int ks = 0; ks < 4; ks++) {
            int kb = ks * 16;
            wmma::fragment<wmma::matrix_a, 16, 16, 16, __nv_bfloat16, wmma::row_major> ah[2], al[2];
            wmma::load_matrix_sync(ah[0], &sAh[(wm * 32 + 0) * GM_LD + kb], GM_LD);
            wmma::load_matrix_sync(ah[1], &sAh[(wm * 32 + 16) * GM_LD + kb], GM_LD);
            wmma::load_matrix_sync(al[0], &sAl[(wm * 32 + 0) * GM_LD + kb], GM_LD);
            wmma::load_matrix_sync(al[1], &sAl[(wm * 32 + 16) * GM_LD + kb], GM_LD);
            wmma::fragment<wmma::matrix_b, 16, 16, 16, __nv_bfloat16, wmma::col_major> bh[4], bl[4];
#pragma unroll
            for (int n = 0; n < 4; n++) {
                wmma::load_matrix_sync(bh[n], &sBh[(wn * 64 + n * 16) * GM_LD + kb], GM_LD);
                wmma::load_matrix_sync(bl[n], &sBl[(wn * 64 + n * 16) * GM_LD + kb], GM_LD);
            }
#pragma unroll
            for (int m = 0; m < 2; m++)
#pragma unroll
                for (int n = 0; n < 4; n++) {
                    wmma::mma_sync(acc[m][n], ah[m], bh[n], acc[m][n]);
                    wmma::mma_sync(acc[m][n], ah[m], bl[n], acc[m][n]);
                    wmma::mma_sync(acc[m][n], al[m], bh[n], acc[m][n]);
                }
        }
    }
    __syncthreads();
#pragma unroll
    for (int m = 0; m < 2; m++)
#pragma unroll
        for (int n = 0; n < 4; n++)
            wmma::store_matrix_sync(&sE[(wm * 32 + m * 16) * GM_ELD + wn * 64 + n * 16],
                                    acc[m][n], GM_ELD, wmma::mem_row_major);
    __syncthreads();

    int b = r0 >> 14;
    int p0 = r0 & (HWc - 1);
    for (int e = tid; e < 128 * 32; e += 256) {
        int r = e >> 5, cq = e & 31;
        float4 v = *(float4*)&sE[r * GM_ELD + cq * 4];
        float bv = bias[ot * 128 + r];
        v.x += bv; v.y += bv; v.z += bv; v.w += bv;
        *(float4*)&out[(((size_t)(b * Oc + ot * 128 + r)) << 14) + p0 + cq * 4] = v;
    }
}

// ---------------- launch ----------------
extern "C" void kernel_launch(void* const* d_in, const int* in_sizes, int n_in,
                              void* d_out, int out_size) {
    const float* x      = (const float*)d_in[0];
    const float* w_off  = (const float*)d_in[1];
    const float* b_off  = (const float*)d_in[2];
    const float* weight = (const float*)d_in[3];
    const float* bias   = (const float*)d_in[4];
    float* out = (float*)d_out;

    cudaFuncSetAttribute(k_conv_mma, cudaFuncAttributeMaxDynamicSharedMemorySize, CV_SMEM);
    cudaFuncSetAttribute(k_gemm_mma, cudaFuncAttributeMaxDynamicSharedMemorySize, GM_SMEM);

    k_transpose<<<dim3(512, 8, 2), dim3(32, 8)>>>(x);
    k_prep_w<<<288, 256>>>(w_off, weight);
    k_conv_mma<<<Bc * Hc, 256, CV_SMEM>>>(b_off);
    k_softmax_stats<<<18, 256>>>();
    k_gather<<<dim3(1024, 2), 256>>>();
    k_gemm_mma<<<dim3(256, 2), 256, GM_SMEM>>>(out, bias);
}